// round 6
// baseline (speedup 1.0000x reference)
#include <cuda_runtime.h>
#include <cstddef>

#define D    512
#define Tt   4096
#define BSZ  8
#define C1   16
#define NCH1 256            // Tt / C1  (chunks per batch, level 1)
#define N1   (BSZ * NCH1)   // 2048 level-1 columns
#define C2   16
#define NCH2 16             // NCH1 / C2
#define N2   (BSZ * NCH2)   // 128 level-2 columns

// ------------- device scratch (static; no allocations) -------------
__device__ float g_P0[D * D];
__device__ float g_P1[D * D];
__device__ float g_A16[D * D];
__device__ float g_A256[D * D];
__device__ float g_CB[N1 * D];   // level-2 state / level-1 carries, col-major (b*256+j)*D
__device__ float g_S[N2 * D];    // level-3 states (b*16+m)*D
__device__ float g_F0[N1 * D];   // fixup ping
__device__ float g_F1[N1 * D];   // fixup pong

__device__ __forceinline__ float* gsel(int s, const float* ext) {
    switch (s) {
        case 0:  return (float*)ext;
        case 1:  return g_P0;
        case 2:  return g_P1;
        case 3:  return g_A16;
        case 4:  return g_A256;
        case 5:  return g_CB;
        case 6:  return g_S;
        case 7:  return g_F0;
        default: return g_F1;
    }
}

// modes
#define M_BX   0   // Y[:,col] = A*X[:,col],  X packed (xsel+col*D), Y packed write (osel)
#define M_SQ   1   // Y = A*X, X strided cols (xsel + col, stride D), Y row-major write
#define M_SCAN 2   // Y[:,t(i)] = A*Y[:,t(i-1)] + Y[:,t(i)]   (in-place scan on osel buffer)
#define M_FIX  3   // P' = A*Pin(xsel packed); write P'(psel packed); osel[:,t(i)] += P'

// ---------------------------------------------------------------------------
// Unified step GEMM.  Block tile: 64 rows x CPB cols, thread tile 8 x CPT.
// Threads = 8*(CPB/CPT).  k-tile 16, double-buffered smem, K = D = 512.
// ---------------------------------------------------------------------------
template <int CPB, int CPT>
__global__ void __launch_bounds__(8 * (CPB / CPT)) gstep(
    const float* __restrict__ Aext, int a_sel,
    const float* __restrict__ Xext, int x_sel,
    float* __restrict__ Oext, int o_sel,
    int p_sel,
    int mode, int Tl, int Cl, int NCHl, int i)
{
    constexpr int NT   = 8 * (CPB / CPT);
    constexpr int A_F4 = 64 * 16 / 4;       // 256
    constexpr int X_F4 = 16 * CPB / 4;      // 4*CPB
    constexpr int A_IT = A_F4 / NT;
    constexpr int X_IT = X_F4 / NT;
    constexpr int NKT  = D / 16;            // 32

    __shared__ float As[2][16][64];
    __shared__ float Xs[2][16][CPB];

    const float* Amat = gsel(a_sel, Aext);
    const float* Xb   = gsel(x_sel, Xext);
    float*       Ob   = gsel(o_sel, Oext);
    float*       Pb   = gsel(p_sel, nullptr);

    const int tid   = threadIdx.x;
    const int e0blk = blockIdx.y * 64;
    const int c0blk = blockIdx.x * CPB;

    // ---- per-thread load assignments ----
    int ae[A_IT], akg[A_IT];
    const float* aptr[A_IT];
#pragma unroll
    for (int q = 0; q < A_IT; q++) {
        int ai = tid + q * NT;
        ae[q]  = ai % 64;
        akg[q] = (ai / 64) * 4;
        aptr[q] = Amat + (size_t)(e0blk + ae[q]) * D + akg[q];
    }
    int xc[X_IT], xkg[X_IT];
    const float* xptr[X_IT];
#pragma unroll
    for (int q = 0; q < X_IT; q++) {
        int xi = tid + q * NT;
        xc[q]  = xi % CPB;
        xkg[q] = (xi / CPB) * 4;
        int col = c0blk + xc[q];
        if (mode == M_SCAN) {
            int b = col / NCHl, j = col % NCHl;
            xptr[q] = Ob + ((size_t)b * Tl + (size_t)j * Cl + (i - 1)) * D;
        } else if (mode == M_SQ) {
            xptr[q] = Xb + col;             // element k at [k*D]
        } else {
            xptr[q] = Xb + (size_t)col * D; // packed
        }
    }

    const int tx = tid % (CPB / CPT);
    const int ty = tid / (CPB / CPT);

    float acc[8][CPT];
#pragma unroll
    for (int r = 0; r < 8; r++)
#pragma unroll
        for (int c = 0; c < CPT; c++) acc[r][c] = 0.f;

    float4 rA[A_IT], rX[X_IT];
    const bool strided = (mode == M_SQ);

    // prologue: tile 0
#pragma unroll
    for (int q = 0; q < A_IT; q++) rA[q] = *(const float4*)(aptr[q]);
#pragma unroll
    for (int q = 0; q < X_IT; q++) {
        if (strided) {
            const float* p = xptr[q];
            int k = xkg[q];
            rX[q] = make_float4(p[(size_t)k * D], p[(size_t)(k + 1) * D],
                                p[(size_t)(k + 2) * D], p[(size_t)(k + 3) * D]);
        } else {
            rX[q] = *(const float4*)(xptr[q] + xkg[q]);
        }
    }
#pragma unroll
    for (int q = 0; q < A_IT; q++) {
        As[0][akg[q] + 0][ae[q]] = rA[q].x; As[0][akg[q] + 1][ae[q]] = rA[q].y;
        As[0][akg[q] + 2][ae[q]] = rA[q].z; As[0][akg[q] + 3][ae[q]] = rA[q].w;
    }
#pragma unroll
    for (int q = 0; q < X_IT; q++) {
        Xs[0][xkg[q] + 0][xc[q]] = rX[q].x; Xs[0][xkg[q] + 1][xc[q]] = rX[q].y;
        Xs[0][xkg[q] + 2][xc[q]] = rX[q].z; Xs[0][xkg[q] + 3][xc[q]] = rX[q].w;
    }
    __syncthreads();

    for (int kt = 0; kt < NKT; kt++) {
        const int cur  = kt & 1;
        const bool more = (kt + 1 < NKT);
        if (more) {
            const int ko = (kt + 1) * 16;
#pragma unroll
            for (int q = 0; q < A_IT; q++) rA[q] = *(const float4*)(aptr[q] + ko);
#pragma unroll
            for (int q = 0; q < X_IT; q++) {
                if (strided) {
                    const float* p = xptr[q];
                    int k = ko + xkg[q];
                    rX[q] = make_float4(p[(size_t)k * D], p[(size_t)(k + 1) * D],
                                        p[(size_t)(k + 2) * D], p[(size_t)(k + 3) * D]);
                } else {
                    rX[q] = *(const float4*)(xptr[q] + ko + xkg[q]);
                }
            }
        }
#pragma unroll
        for (int k = 0; k < 16; k++) {
            float a[8];
            *(float4*)&a[0] = *(const float4*)&As[cur][k][ty * 8];
            *(float4*)&a[4] = *(const float4*)&As[cur][k][ty * 8 + 4];
            float xv[CPT];
            if constexpr (CPT == 8) {
                *(float4*)&xv[0] = *(const float4*)&Xs[cur][k][tx * 8];
                *(float4*)&xv[4] = *(const float4*)&Xs[cur][k][tx * 8 + 4];
            } else {
                *(float4*)&xv[0] = *(const float4*)&Xs[cur][k][tx * 4];
            }
#pragma unroll
            for (int r = 0; r < 8; r++)
#pragma unroll
                for (int c = 0; c < CPT; c++) acc[r][c] += a[r] * xv[c];
        }
        if (more) {
            const int nxt = 1 - cur;
#pragma unroll
            for (int q = 0; q < A_IT; q++) {
                As[nxt][akg[q] + 0][ae[q]] = rA[q].x; As[nxt][akg[q] + 1][ae[q]] = rA[q].y;
                As[nxt][akg[q] + 2][ae[q]] = rA[q].z; As[nxt][akg[q] + 3][ae[q]] = rA[q].w;
            }
#pragma unroll
            for (int q = 0; q < X_IT; q++) {
                Xs[nxt][xkg[q] + 0][xc[q]] = rX[q].x; Xs[nxt][xkg[q] + 1][xc[q]] = rX[q].y;
                Xs[nxt][xkg[q] + 2][xc[q]] = rX[q].z; Xs[nxt][xkg[q] + 3][xc[q]] = rX[q].w;
            }
            __syncthreads();
        }
    }

    // ---- writeback ----
    const int e0 = e0blk + ty * 8;
#pragma unroll
    for (int c = 0; c < CPT; c++) {
        const int col = c0blk + tx * CPT + c;
        float4 v0 = make_float4(acc[0][c], acc[1][c], acc[2][c], acc[3][c]);
        float4 v1 = make_float4(acc[4][c], acc[5][c], acc[6][c], acc[7][c]);
        if (mode == M_BX) {
            float* d = Ob + (size_t)col * D + e0;
            *(float4*)d = v0; *(float4*)(d + 4) = v1;
        } else if (mode == M_SQ) {
#pragma unroll
            for (int r = 0; r < 8; r++)
                Ob[(size_t)(e0 + r) * D + col] = acc[r][c];
        } else {
            int b = col / NCHl, j = col % NCHl;
            float* d = Ob + ((size_t)b * Tl + (size_t)j * Cl + i) * D + e0;
            if (mode == M_FIX) {
                float* po = Pb + (size_t)col * D + e0;
                *(float4*)po = v0; *(float4*)(po + 4) = v1;
            }
            float4 u0 = *(const float4*)d;
            float4 u1 = *(const float4*)(d + 4);
            u0.x += v0.x; u0.y += v0.y; u0.z += v0.z; u0.w += v0.w;
            u1.x += v1.x; u1.y += v1.y; u1.z += v1.z; u1.w += v1.w;
            *(float4*)d = u0; *(float4*)(d + 4) = u1;
        }
    }
}

// ---------------- init level-2 inputs: CB[b,0]=h0; CB[b,j]=out[b,16j-1] ----------------
__global__ void init_cb(const float* __restrict__ h0, const float* __restrict__ out) {
    int idx = blockIdx.x * blockDim.x + threadIdx.x;   // over N1*D = 1M
    int col = idx / D, e = idx % D;
    int b = col / NCH1, j = col % NCH1;
    float v = (j == 0) ? h0[(size_t)b * D + e]
                       : out[((size_t)b * Tt + (size_t)j * C1 - 1) * D + e];
    g_CB[idx] = v;
}

// ---------------- level-3: per-batch sequential scan of 16 super-carries ----------------
// s_0 = 0;  s_m = A^256 * s_{m-1} + CB[b, 16m-1];  stored in g_S[b,m]
__global__ void __launch_bounds__(D) l3_scan() {
    __shared__ float s[D];
    const int b = blockIdx.x;     // 8
    const int t = threadIdx.x;    // 512
    g_S[(size_t)b * NCH2 * D + t] = 0.f;
    s[t] = 0.f;
    __syncthreads();
    for (int m = 1; m < NCH2; m++) {
        const float* arow = g_A256 + (size_t)t * D;
        float acc = 0.f;
#pragma unroll 8
        for (int k = 0; k < D; k += 4) {
            float4 a = *(const float4*)(arow + k);
            acc += a.x * s[k] + a.y * s[k + 1] + a.z * s[k + 2] + a.w * s[k + 3];
        }
        acc += g_CB[((size_t)b * NCH1 + (m * C2 - 1)) * D + t];
        __syncthreads();
        s[t] = acc;
        g_S[((size_t)b * NCH2 + m) * D + t] = acc;
        __syncthreads();
    }
}

// ---------------- launcher ----------------
extern "C" void kernel_launch(void* const* d_in, const int* in_sizes, int n_in,
                              void* d_out, int out_size) {
    (void)in_sizes; (void)n_in; (void)out_size;
    const float* x  = (const float*)d_in[0];   // [8, 4096, 512]
    const float* h0 = (const float*)d_in[1];   // [8, 512]
    const float* A  = (const float*)d_in[2];   // [512, 512]
    const float* Bm = (const float*)d_in[3];   // [512, 512]
    float* out = (float*)d_out;                // [8, 4096, 512]

    const dim3 gSQ(D / 128, 8);          // 32 blocks
    const dim3 gBX((BSZ * Tt) / 128, 8); // 2048 blocks
    const dim3 gL1(N1 / 128, 8);         // 128 blocks
    const dim3 gL2(N2 / 32, 8);          // 32 blocks

    // K1: out = Bx   (Y[:,m] = B * x[m,:])
    gstep<128, 8><<<gBX, 128>>>(Bm, 0, x, 0, out, 0, 0, M_BX, 0, 0, 0, 0);

    // K2: powers by squaring: A^2..A^16, A^32..A^256
    gstep<128, 8><<<gSQ, 128>>>(A, 0, A, 0, nullptr, 1, 0, M_SQ, 0, 0, 0, 0);       // P0 = A^2
    gstep<128, 8><<<gSQ, 128>>>(nullptr, 1, nullptr, 1, nullptr, 2, 0, M_SQ, 0, 0, 0, 0); // P1 = A^4
    gstep<128, 8><<<gSQ, 128>>>(nullptr, 2, nullptr, 2, nullptr, 1, 0, M_SQ, 0, 0, 0, 0); // P0 = A^8
    gstep<128, 8><<<gSQ, 128>>>(nullptr, 1, nullptr, 1, nullptr, 3, 0, M_SQ, 0, 0, 0, 0); // A16
    gstep<128, 8><<<gSQ, 128>>>(nullptr, 3, nullptr, 3, nullptr, 1, 0, M_SQ, 0, 0, 0, 0); // P0 = A^32
    gstep<128, 8><<<gSQ, 128>>>(nullptr, 1, nullptr, 1, nullptr, 2, 0, M_SQ, 0, 0, 0, 0); // P1 = A^64
    gstep<128, 8><<<gSQ, 128>>>(nullptr, 2, nullptr, 2, nullptr, 1, 0, M_SQ, 0, 0, 0, 0); // P0 = A^128
    gstep<128, 8><<<gSQ, 128>>>(nullptr, 1, nullptr, 1, nullptr, 4, 0, M_SQ, 0, 0, 0, 0); // A256

    // K3: level-1 local scan (15 fat steps, in place in out)
    for (int i = 1; i < C1; i++)
        gstep<128, 8><<<gL1, 128>>>(A, 0, nullptr, 0, out, 0, 0, M_SCAN, Tt, C1, NCH1, i);

    // K4: level-2 inputs
    init_cb<<<(N1 * D) / 256, 256>>>(h0, out);

    // K5: level-2 local scan on CB with A^16
    for (int i = 1; i < C2; i++)
        gstep<32, 4><<<gL2, 64>>>(nullptr, 3, nullptr, 0, nullptr, 5, 0, M_SCAN, NCH1, C2, NCH2, i);

    // K6: level-3 boundary (persistent, per-batch independent)
    l3_scan<<<BSZ, D>>>();

    // K7: level-2 fixup: P <- A^16 * P (P starts = S), CB[:, 16m+i] += P
    for (int i = 0; i < C2; i++) {
        int pin  = (i == 0) ? 6 : ((i & 1) ? 7 : 8);
        int pout = (i & 1) ? 8 : 7;
        gstep<32, 4><<<gL2, 64>>>(nullptr, 3, nullptr, pin, nullptr, 5, pout,
                                  M_FIX, NCH1, C2, NCH2, i);
    }

    // K8: level-1 fixup: P <- A * P (P starts = CB = carries), out[:, 16j+i] += P
    for (int i = 0; i < C1; i++) {
        int pin  = (i == 0) ? 5 : ((i & 1) ? 7 : 8);
        int pout = (i & 1) ? 8 : 7;
        gstep<128, 8><<<gL1, 128>>>(A, 0, nullptr, pin, out, 0, pout,
                                    M_FIX, Tt, C1, NCH1, i);
    }
}

// round 7
// speedup vs baseline: 1.7409x; 1.7409x over previous
#include <cuda_runtime.h>
#include <cstddef>
#include <cstdint>

#define D    512
#define DDm  (D * D)
#define Tt   4096
#define BSZ  8
#define KT   16
#define NKT  (D / KT)      // 32

// ---------------- static device scratch (no allocations) ----------------
// g_POW slots: 0..7 = A^1..A^8 ; 7..14 = A^8,A^16,...,A^64 ; 14..21 = A^64,...,A^512
__device__ float g_POW[22 * DDm];          // 22 MB
__device__ float g_CB[BSZ * 512 * D];      // level-2 sequence (c_j inputs/states)
__device__ float g_DB[BSZ * 64 * D];       // level-3 sequence
__device__ float g_EB[BSZ * 8 * D];        // level-4 sequence

enum { M_BX = 0, M_POW = 1, M_SCAN = 2, M_FIXZ = 3 };

__device__ __forceinline__ int i4sel(int4 v, int z) {
    return (z == 0) ? v.x : (z == 1) ? v.y : (z == 2) ? v.z : v.w;
}

// ---------------------------------------------------------------------------
// Unified GEMM step.  Block tile 128 rows x CPB cols, 256 threads, thread tile
// 8 x CPT (CPB/CPT == 16).  k-tile 16, double-buffered smem, K = D = 512.
// Modes:
//   M_BX   : O[:,c] = A * X[:,c]            (X,O packed col-major at c*D)
//   M_POW  : POW[zd] = POW[za] * POW[zx]    (row-major matrices, z-batched)
//   M_SCAN : O[:,t(c,i)] = A*O[:,t(c,i-1)] + O[:,t(c,i)]  (in-place chunked scan)
//            fold: at i==Cl-1 also write result to Pfold[:, chunk+1]
//   M_FIXZ : O[:,t(c,z)] += (Abase + z*DDm) * X[:,c]      (z-batched fixup)
// ---------------------------------------------------------------------------
template <int CPB, int CPT>
__global__ void __launch_bounds__(256, 2) gstep(
    const float* __restrict__ Abase,
    const float* __restrict__ Xbase,
    float* __restrict__ Obase,
    float* __restrict__ Pfold,
    int mode, int i, int Tl, int Cl, int shN, int shS,
    int4 za, int4 zx, int4 zd)
{
    __shared__ float As[2][KT][132];
    __shared__ float Xs[2][KT][CPB + 4];

    const int tid = threadIdx.x;
    const int e0  = blockIdx.y * 128;
    const int c0  = blockIdx.x * CPB;
    const int z   = blockIdx.z;

    const float* Amat;
    const float* Xmat = Xbase;
    float* Ymat = Obase;
    if (mode == M_POW) {
        Amat = Abase + (size_t)i4sel(za, z) * DDm;
        Xmat = Xbase + (size_t)i4sel(zx, z) * DDm;
        Ymat = Obase + (size_t)i4sel(zd, z) * DDm;
    } else if (mode == M_FIXZ) {
        Amat = Abase + (size_t)z * DDm;
    } else {
        Amat = Abase;
    }

    // ---- A row pointers (2 iters of 64 rows) ----
    const int ar = tid >> 2;              // 0..63
    const int ak = (tid & 3) * 4;         // 0,4,8,12
    const float* ap0 = Amat + (size_t)(e0 + ar) * D + ak;
    const float* ap1 = ap0 + (size_t)64 * D;

    // ---- X pointers ----
    const float* xp0 = nullptr;
    const float* xp1 = nullptr;
    const float* xr0 = nullptr;
    const float* xr1 = nullptr;
    bool xa0 = false, xa1 = false;
    int xk = 0, xc = 0;
    if (mode == M_POW) {
        xk = tid >> 5;                    // 0..7
        xc = (tid & 31) * 4;              // 0..124
        xr0 = Xmat + (size_t)xk * D + c0 + xc;
        xr1 = xr0 + (size_t)8 * D;
    } else {
        const int cl0 = tid >> 2;         // 0..63
        if (cl0 < CPB) {
            xa0 = true;
            const int c = c0 + cl0;
            if (mode == M_SCAN) {
                const int b = c >> shN, j = c & ((1 << shN) - 1);
                xp0 = Obase + ((size_t)b * Tl + (size_t)j * Cl + (i - 1)) * D + ak;
            } else {
                xp0 = Xmat + (size_t)c * D + ak;
            }
        }
        if (CPB == 128) {
            xa1 = true;
            const int c = c0 + (tid >> 2) + 64;
            if (mode == M_SCAN) {
                const int b = c >> shN, j = c & ((1 << shN) - 1);
                xp1 = Obase + ((size_t)b * Tl + (size_t)j * Cl + (i - 1)) * D + ak;
            } else {
                xp1 = Xmat + (size_t)c * D + ak;
            }
        }
    }

    const int tx = tid & 15;
    const int ty = tid >> 4;

    float acc[8][CPT];
#pragma unroll
    for (int r = 0; r < 8; r++)
#pragma unroll
        for (int cc = 0; cc < CPT; cc++) acc[r][cc] = 0.f;

    float4 rA0, rA1, rX0, rX1;

#define FETCH(KO)                                                         \
    do {                                                                  \
        rA0 = *(const float4*)(ap0 + (KO));                               \
        rA1 = *(const float4*)(ap1 + (KO));                               \
        if (mode == M_POW) {                                              \
            rX0 = *(const float4*)(xr0 + (size_t)(KO) * D);               \
            rX1 = *(const float4*)(xr1 + (size_t)(KO) * D);               \
        } else {                                                          \
            if (xa0) rX0 = *(const float4*)(xp0 + (KO));                  \
            if (xa1) rX1 = *(const float4*)(xp1 + (KO));                  \
        }                                                                 \
    } while (0)

#define STASH(BF)                                                         \
    do {                                                                  \
        As[BF][ak + 0][ar] = rA0.x; As[BF][ak + 1][ar] = rA0.y;           \
        As[BF][ak + 2][ar] = rA0.z; As[BF][ak + 3][ar] = rA0.w;           \
        As[BF][ak + 0][ar + 64] = rA1.x; As[BF][ak + 1][ar + 64] = rA1.y; \
        As[BF][ak + 2][ar + 64] = rA1.z; As[BF][ak + 3][ar + 64] = rA1.w; \
        if (mode == M_POW) {                                              \
            *(float4*)&Xs[BF][xk][xc]     = rX0;                          \
            *(float4*)&Xs[BF][xk + 8][xc] = rX1;                          \
        } else {                                                          \
            if (xa0) {                                                    \
                const int cl = tid >> 2;                                  \
                Xs[BF][ak + 0][cl] = rX0.x; Xs[BF][ak + 1][cl] = rX0.y;   \
                Xs[BF][ak + 2][cl] = rX0.z; Xs[BF][ak + 3][cl] = rX0.w;   \
            }                                                             \
            if (xa1) {                                                    \
                const int cl = (tid >> 2) + 64;                           \
                Xs[BF][ak + 0][cl] = rX1.x; Xs[BF][ak + 1][cl] = rX1.y;   \
                Xs[BF][ak + 2][cl] = rX1.z; Xs[BF][ak + 3][cl] = rX1.w;   \
            }                                                             \
        }                                                                 \
    } while (0)

#define TILE(BF)                                                          \
    do {                                                                  \
        _Pragma("unroll")                                                 \
        for (int kk = 0; kk < KT; kk++) {                                 \
            float a[8];                                                   \
            *(float4*)&a[0] = *(const float4*)&As[BF][kk][ty * 8];        \
            *(float4*)&a[4] = *(const float4*)&As[BF][kk][ty * 8 + 4];    \
            float xv[CPT];                                                \
            if constexpr (CPT == 8) {                                     \
                *(float4*)&xv[0] = *(const float4*)&Xs[BF][kk][tx * 8];   \
                *(float4*)&xv[4] = *(const float4*)&Xs[BF][kk][tx * 8 + 4]; \
            } else if constexpr (CPT == 2) {                              \
                *(float2*)&xv[0] = *(const float2*)&Xs[BF][kk][tx * 2];   \
            } else {                                                      \
                xv[0] = Xs[BF][kk][tx];                                   \
            }                                                             \
            _Pragma("unroll")                                             \
            for (int r = 0; r < 8; r++)                                   \
                _Pragma("unroll")                                         \
                for (int cc = 0; cc < CPT; cc++)                          \
                    acc[r][cc] += a[r] * xv[cc];                          \
        }                                                                 \
    } while (0)

    FETCH(0);
    STASH(0);
    __syncthreads();
    for (int kt = 0; kt < NKT - 1; kt++) {
        FETCH((kt + 1) * KT);
        TILE(kt & 1);
        STASH((kt + 1) & 1);
        __syncthreads();
    }
    TILE((NKT - 1) & 1);

    // ---------------- writeback ----------------
    const int er = e0 + ty * 8;
    if (mode == M_BX) {
        const int col0 = c0 + tx * CPT;
#pragma unroll
        for (int cc = 0; cc < CPT; cc++) {
            float* dp = Obase + (size_t)(col0 + cc) * D + er;
            *(float4*)dp       = make_float4(acc[0][cc], acc[1][cc], acc[2][cc], acc[3][cc]);
            *(float4*)(dp + 4) = make_float4(acc[4][cc], acc[5][cc], acc[6][cc], acc[7][cc]);
        }
    } else if (mode == M_POW) {
#pragma unroll
        for (int r = 0; r < 8; r++) {
            float* dp = Ymat + (size_t)(er + r) * D + c0 + tx * CPT;
#pragma unroll
            for (int cc = 0; cc < CPT; cc += 4)
                *(float4*)(dp + cc) = make_float4(acc[r][cc], acc[r][cc + 1],
                                                  acc[r][cc + 2], acc[r][cc + 3]);
        }
    } else if (mode == M_SCAN) {
#pragma unroll
        for (int cc = 0; cc < CPT; cc++) {
            const int c = c0 + tx * CPT + cc;
            const int b = c >> shN, j = c & ((1 << shN) - 1);
            float* dp = Obase + ((size_t)b * Tl + (size_t)j * Cl + i) * D + er;
            float4 u0 = *(const float4*)dp;
            float4 u1 = *(const float4*)(dp + 4);
            u0.x += acc[0][cc]; u0.y += acc[1][cc]; u0.z += acc[2][cc]; u0.w += acc[3][cc];
            u1.x += acc[4][cc]; u1.y += acc[5][cc]; u1.z += acc[6][cc]; u1.w += acc[7][cc];
            *(float4*)dp = u0; *(float4*)(dp + 4) = u1;
            if (i == Cl - 1 && j < (1 << shN) - 1) {
                float* fp = Pfold + ((size_t)b * (1 << shN) + j + 1) * D + er;
                *(float4*)fp = u0; *(float4*)(fp + 4) = u1;
            }
        }
    } else {  // M_FIXZ
#pragma unroll
        for (int cc = 0; cc < CPT; cc++) {
            const int c = c0 + tx * CPT + cc;
            const int b = c >> shS, ch = c & ((1 << shS) - 1);
            float* dp = Obase + ((size_t)b * Tl + (size_t)ch * Cl + z) * D + er;
            float4 u0 = *(const float4*)dp;
            float4 u1 = *(const float4*)(dp + 4);
            u0.x += acc[0][cc]; u0.y += acc[1][cc]; u0.z += acc[2][cc]; u0.w += acc[3][cc];
            u1.x += acc[4][cc]; u1.y += acc[5][cc]; u1.z += acc[6][cc]; u1.w += acc[7][cc];
            *(float4*)dp = u0; *(float4*)(dp + 4) = u1;
        }
    }
#undef FETCH
#undef STASH
#undef TILE
}

// ---------------- seeds: CB[b,0] = h0, DB[b,0] = EB[b,0] = 0 ----------------
__global__ void seed_levels(const float* __restrict__ h0) {
    const int b = blockIdx.x, t = threadIdx.x;
    g_CB[(size_t)b * 512 * D + t] = h0[(size_t)b * D + t];
    g_DB[(size_t)b * 64 * D + t]  = 0.f;
    g_EB[(size_t)b * 8 * D + t]   = 0.f;
}

// ---------------- level-4: per-batch sequential scan of 8 states, A^512 ----------------
__global__ void __launch_bounds__(512) l4_scan() {
    __shared__ float s[D];
    const int b = blockIdx.x, t = threadIdx.x;
    const float* A512 = g_POW + (size_t)21 * DDm;
    s[t] = 0.f;      // e_0 = 0 (EB[b,0] stays 0 from seed)
    __syncthreads();
    for (int p = 1; p < 8; p++) {
        const float* row = A512 + (size_t)t * D;
        float acc = 0.f;
#pragma unroll 8
        for (int k = 0; k < D; k += 4) {
            float4 a = *(const float4*)(row + k);
            acc += a.x * s[k] + a.y * s[k + 1] + a.z * s[k + 2] + a.w * s[k + 3];
        }
        acc += g_EB[((size_t)b * 8 + p) * D + t];
        __syncthreads();
        s[t] = acc;
        g_EB[((size_t)b * 8 + p) * D + t] = acc;
        __syncthreads();
    }
}

// ---------------- launcher ----------------
extern "C" void kernel_launch(void* const* d_in, const int* in_sizes, int n_in,
                              void* d_out, int out_size) {
    (void)in_sizes; (void)n_in; (void)out_size;
    const float* x  = (const float*)d_in[0];   // [8, 4096, 512]
    const float* h0 = (const float*)d_in[1];   // [8, 512]
    const float* A  = (const float*)d_in[2];   // [512, 512]
    const float* Bm = (const float*)d_in[3];   // [512, 512]
    float* out = (float*)d_out;                // [8, 4096, 512]

    static float* pPOW = nullptr;
    static float *pCB, *pDB, *pEB;
    if (!pPOW) {
        cudaGetSymbolAddress((void**)&pPOW, g_POW);
        cudaGetSymbolAddress((void**)&pCB, g_CB);
        cudaGetSymbolAddress((void**)&pDB, g_DB);
        cudaGetSymbolAddress((void**)&pEB, g_EB);
    }
    const int4 zz = make_int4(0, 0, 0, 0);

    // K1: out = Bx  (32768 columns)
    gstep<128, 8><<<dim3(256, 4, 1), 256>>>(Bm, x, out, nullptr, M_BX,
                                            0, 0, 0, 0, 0, zz, zz, zz);

    // K2: level-1 local scan (7 steps, 4096 cols each), fold chunk-ends -> CB
    for (int i = 1; i < 8; i++)
        gstep<128, 8><<<dim3(32, 4, 1), 256>>>(A, nullptr, out, pCB, M_SCAN,
                                               i, Tt, 8, 9, 0, zz, zz, zz);

    // K3: seeds
    seed_levels<<<BSZ, D>>>(h0);

    // K4: power tables. slot0 = A, then batched squaring/multiplies.
    cudaMemcpyAsync(pPOW, A, (size_t)DDm * sizeof(float), cudaMemcpyDeviceToDevice);
#define POWL(ZC, AZ, XZ, DZ)                                                        \
    gstep<128, 8><<<dim3(4, 4, ZC), 256>>>(pPOW, pPOW, pPOW, nullptr, M_POW,        \
                                           0, 0, 0, 0, 0, AZ, XZ, DZ)
    POWL(1, make_int4(0,0,0,0),      make_int4(0,0,0,0),      make_int4(1,0,0,0));     // A^2
    POWL(2, make_int4(1,1,0,0),      make_int4(0,1,0,0),      make_int4(2,3,0,0));     // A^3, A^4
    POWL(4, make_int4(3,3,3,3),      make_int4(0,1,2,3),      make_int4(4,5,6,7));     // A^5..A^8
    POWL(1, make_int4(7,0,0,0),      make_int4(7,0,0,0),      make_int4(8,0,0,0));     // A^16
    POWL(2, make_int4(8,8,0,0),      make_int4(7,8,0,0),      make_int4(9,10,0,0));    // A^24, A^32
    POWL(4, make_int4(10,10,10,10),  make_int4(7,8,9,10),     make_int4(11,12,13,14)); // A^40..A^64
    POWL(1, make_int4(14,0,0,0),     make_int4(14,0,0,0),     make_int4(15,0,0,0));    // A^128
    POWL(2, make_int4(15,15,0,0),    make_int4(14,15,0,0),    make_int4(16,17,0,0));   // A^192, A^256
    POWL(4, make_int4(17,17,17,17),  make_int4(14,15,16,17),  make_int4(18,19,20,21)); // A^320..A^512
#undef POWL

    // K5: level-2 local scan on CB (transition A^8), fold -> DB
    for (int i = 1; i < 8; i++)
        gstep<32, 2><<<dim3(16, 4, 1), 256>>>(pPOW + (size_t)7 * DDm, nullptr, pCB,
                                              pDB, M_SCAN, i, 512, 8, 6, 0, zz, zz, zz);

    // K6: level-3 local scan on DB (transition A^64), fold -> EB
    for (int i = 1; i < 8; i++)
        gstep<16, 1><<<dim3(4, 4, 1), 256>>>(pPOW + (size_t)14 * DDm, nullptr, pDB,
                                             pEB, M_SCAN, i, 64, 8, 3, 0, zz, zz, zz);

    // K7: level-4 boundary scan (A^512), in place in EB
    l4_scan<<<BSZ, D>>>();

    // K8: level-3 fixup  DB[:, 8p+z] += A^{64(z+1)} * EB[:, p]   (one launch, z=0..7)
    gstep<16, 1><<<dim3(4, 4, 8), 256>>>(pPOW + (size_t)14 * DDm, pEB, pDB, nullptr,
                                         M_FIXZ, 0, 64, 8, 0, 3, zz, zz, zz);

    // K9: level-2 fixup  CB[:, 8m+z] += A^{8(z+1)} * DB[:, m]
    gstep<128, 8><<<dim3(4, 4, 8), 256>>>(pPOW + (size_t)7 * DDm, pDB, pCB, nullptr,
                                          M_FIXZ, 0, 512, 8, 0, 6, zz, zz, zz);

    // K10: level-1 fixup  out[:, 8j+z] += A^{z+1} * CB[:, j]   (one fat launch)
    gstep<128, 8><<<dim3(32, 4, 8), 256>>>(pPOW, pCB, out, nullptr,
                                           M_FIXZ, 0, Tt, 8, 0, 9, zz, zz, zz);
}

// round 10
// speedup vs baseline: 2.7910x; 1.6032x over previous
#include <cuda_runtime.h>
#include <cuda_bf16.h>
#include <cstdint>
#include <cstddef>

#define D     512
#define DDm   (D * D)
#define Tt    4096
#define BSZ   8
#define NSLOT 23      // 0..7:A^1..A^8  7..14:A^8..A^64  14..21:A^64..A^512  22:B
#define KC    32
#define NCHK  16
#define STRB  40      // smem row stride (bf16 units) -> 80 B, conflict-free ldmatrix
#define AHOF  0
#define ALOF  10240
#define XHOF  20480
#define XLOF  25600
#define STG   30720
#define SMEMSZ (2 * STG)

__device__ __nv_bfloat16 g_PH[NSLOT * DDm];   // powers hi, row-major (A operand)
__device__ __nv_bfloat16 g_PL[NSLOT * DDm];   // lo
__device__ __nv_bfloat16 g_PTH[NSLOT * DDm];  // transposed hi (B operand for POW)
__device__ __nv_bfloat16 g_PTL[NSLOT * DDm];
__device__ float g_Pf[DDm];                   // fp32 A^512 (for l4 scan)
__device__ float g_CB[(BSZ * 512) * D];
__device__ float g_DB[(BSZ * 64) * D];
__device__ float g_EB[(BSZ * 8) * D];

enum { M_BX = 0, M_POW = 1, M_SCAN = 2, M_FIXZ = 3 };

__device__ __forceinline__ int i4sel(int4 v, int z) {
    return (z == 0) ? v.x : (z == 1) ? v.y : (z == 2) ? v.z : v.w;
}
__device__ __forceinline__ uint32_t s2u(const void* p) {
    uint32_t a;
    asm("{ .reg .u64 t; cvta.to.shared.u64 t, %1; cvt.u32.u64 %0, t; }" : "=r"(a) : "l"(p));
    return a;
}
__device__ __forceinline__ void split8(float4 a, float4 b, uint4& H, uint4& L) {
    __nv_bfloat162 h0 = __float22bfloat162_rn(make_float2(a.x, a.y));
    __nv_bfloat162 h1 = __float22bfloat162_rn(make_float2(a.z, a.w));
    __nv_bfloat162 h2 = __float22bfloat162_rn(make_float2(b.x, b.y));
    __nv_bfloat162 h3 = __float22bfloat162_rn(make_float2(b.z, b.w));
    float2 f0 = __bfloat1622float2(h0), f1 = __bfloat1622float2(h1);
    float2 f2 = __bfloat1622float2(h2), f3 = __bfloat1622float2(h3);
    __nv_bfloat162 l0 = __float22bfloat162_rn(make_float2(a.x - f0.x, a.y - f0.y));
    __nv_bfloat162 l1 = __float22bfloat162_rn(make_float2(a.z - f1.x, a.w - f1.y));
    __nv_bfloat162 l2 = __float22bfloat162_rn(make_float2(b.x - f2.x, b.y - f2.y));
    __nv_bfloat162 l3 = __float22bfloat162_rn(make_float2(b.z - f3.x, b.w - f3.y));
    H.x = *(uint32_t*)&h0; H.y = *(uint32_t*)&h1; H.z = *(uint32_t*)&h2; H.w = *(uint32_t*)&h3;
    L.x = *(uint32_t*)&l0; L.y = *(uint32_t*)&l1; L.z = *(uint32_t*)&l2; L.w = *(uint32_t*)&l3;
}
__device__ __forceinline__ void ldm4(uint32_t* r, uint32_t addr) {
    asm volatile("ldmatrix.sync.aligned.m8n8.x4.shared.b16 {%0,%1,%2,%3}, [%4];"
                 : "=r"(r[0]), "=r"(r[1]), "=r"(r[2]), "=r"(r[3]) : "r"(addr));
}
__device__ __forceinline__ void mma16816(float* c, const uint32_t* a, const uint32_t* b) {
    asm volatile("mma.sync.aligned.m16n8k16.row.col.f32.bf16.bf16.f32 "
                 "{%0,%1,%2,%3}, {%4,%5,%6,%7}, {%8,%9}, {%0,%1,%2,%3};"
                 : "+f"(c[0]), "+f"(c[1]), "+f"(c[2]), "+f"(c[3])
                 : "r"(a[0]), "r"(a[1]), "r"(a[2]), "r"(a[3]), "r"(b[0]), "r"(b[1]));
}

// ---------------------------------------------------------------------------
// HMMA unified step: 128 e-rows (blockIdx.y) x 64 cols (blockIdx.x), K = 512.
// 8 warps in 4x2 grid, warp tile 32x32, split-fp32 bf16 3-term accumulation.
// ---------------------------------------------------------------------------
__global__ void __launch_bounds__(256) tstep(
    const float* __restrict__ Xf, float* __restrict__ Of, float* __restrict__ Pf,
    int mode, int i, int Tl, int Cl, int shN, int aslot, int ncols,
    int4 za, int4 zx, int4 zd)
{
    extern __shared__ char smem[];
    const uint32_t sbu = s2u(smem);
    const int tid = threadIdx.x, wid = tid >> 5, l = tid & 31;
    const int e0 = blockIdx.y * 128, c0 = blockIdx.x * 64, z = blockIdx.z;
    const int mask = (1 << shN) - 1;
    const int wm = wid >> 1, wn = wid & 1;

    const int as = (mode == M_POW) ? i4sel(za, z) : (mode == M_FIXZ) ? (aslot + z) : aslot;

    // ---- A loader: 128 rows x 32 k per chunk, hi+lo ----
    const int aRow = tid >> 1, aK = (tid & 1) * 16;
    const __nv_bfloat16* pAH = g_PH + (size_t)as * DDm + (size_t)(e0 + aRow) * D + aK;
    const __nv_bfloat16* pAL = g_PL + (size_t)as * DDm + (size_t)(e0 + aRow) * D + aK;
    const uint32_t sAo = (uint32_t)(aRow * STRB + aK) * 2;

    // ---- X loader ----
    const float* xfp = nullptr;
    const __nv_bfloat16 *pXH = nullptr, *pXL = nullptr;
    uint32_t sXo = 0;
    if (mode == M_POW) {
        if (tid < 128) {
            const int xc = tid >> 1, xk = (tid & 1) * 16;
            const int xs = i4sel(zx, z);
            pXH = g_PTH + (size_t)xs * DDm + (size_t)(c0 + xc) * D + xk;
            pXL = g_PTL + (size_t)xs * DDm + (size_t)(c0 + xc) * D + xk;
            sXo = (uint32_t)(xc * STRB + xk) * 2;
        }
    } else {
        const int xc = tid >> 2, xk = (tid & 3) * 8;
        const int c = c0 + xc;
        if (mode == M_SCAN) {
            const int b = c >> shN, j = c & mask;
            xfp = Of + ((size_t)b * Tl + (size_t)j * Cl + (i - 1)) * D + xk;
        } else {
            xfp = Xf + (size_t)c * D + xk;
        }
        sXo = (uint32_t)(xc * STRB + xk) * 2;
    }

    float acc[2][4][4];
#pragma unroll
    for (int a = 0; a < 2; a++)
#pragma unroll
        for (int b = 0; b < 4; b++)
#pragma unroll
            for (int q = 0; q < 4; q++) acc[a][b][q] = 0.f;

    uint4 rh0, rh1, rl0, rl1, xh0, xh1, xl0, xl1;
    float4 f0, f1;

#define FETCH(CH) do { const int _k = (CH) * KC;                              \
        rh0 = *(const uint4*)(pAH + _k); rh1 = *(const uint4*)(pAH + _k + 8); \
        rl0 = *(const uint4*)(pAL + _k); rl1 = *(const uint4*)(pAL + _k + 8); \
        if (mode == M_POW) { if (tid < 128) {                                 \
            xh0 = *(const uint4*)(pXH + _k); xh1 = *(const uint4*)(pXH + _k + 8); \
            xl0 = *(const uint4*)(pXL + _k); xl1 = *(const uint4*)(pXL + _k + 8); } } \
        else { f0 = *(const float4*)(xfp + _k); f1 = *(const float4*)(xfp + _k + 4); } \
    } while (0)

#define STORE(S) do { char* _b = smem + (S) * STG;                            \
        *(uint4*)(_b + AHOF + sAo) = rh0; *(uint4*)(_b + AHOF + sAo + 16) = rh1; \
        *(uint4*)(_b + ALOF + sAo) = rl0; *(uint4*)(_b + ALOF + sAo + 16) = rl1; \
        if (mode == M_POW) { if (tid < 128) {                                 \
            *(uint4*)(_b + XHOF + sXo) = xh0; *(uint4*)(_b + XHOF + sXo + 16) = xh1; \
            *(uint4*)(_b + XLOF + sXo) = xl0; *(uint4*)(_b + XLOF + sXo + 16) = xl1; } } \
        else { uint4 _H, _L; split8(f0, f1, _H, _L);                          \
            *(uint4*)(_b + XHOF + sXo) = _H; *(uint4*)(_b + XLOF + sXo) = _L; } \
    } while (0)

#define COMPUTE(S) do { const uint32_t stb = sbu + (S) * STG;                 \
        _Pragma("unroll")                                                     \
        for (int ks = 0; ks < 2; ks++) {                                      \
            const int k0 = ks * 16;                                           \
            uint32_t bh[4][2], bl[4][2];                                      \
            _Pragma("unroll")                                                 \
            for (int p = 0; p < 2; p++) {                                     \
                const uint32_t nrow = wn * 32 + p * 16 + (l & 7) + ((l >> 4) << 3); \
                const uint32_t koff = k0 + (((l >> 3) & 1) << 3);             \
                const uint32_t ax = stb + XHOF + (nrow * STRB + koff) * 2;    \
                uint32_t r[4];                                                \
                ldm4(r, ax);                                                  \
                bh[2*p][0] = r[0]; bh[2*p][1] = r[1];                         \
                bh[2*p+1][0] = r[2]; bh[2*p+1][1] = r[3];                     \
                ldm4(r, ax + (XLOF - XHOF));                                  \
                bl[2*p][0] = r[0]; bl[2*p][1] = r[1];                         \
                bl[2*p+1][0] = r[2]; bl[2*p+1][1] = r[3];                     \
            }                                                                 \
            _Pragma("unroll")                                                 \
            for (int mt = 0; mt < 2; mt++) {                                  \
                const uint32_t mrow = wm * 32 + mt * 16 + (l & 15);           \
                const uint32_t koffA = k0 + ((l >> 4) << 3);                  \
                const uint32_t aa = stb + AHOF + (mrow * STRB + koffA) * 2;   \
                uint32_t ah[4], al[4];                                        \
                ldm4(ah, aa); ldm4(al, aa + (ALOF - AHOF));                   \
                _Pragma("unroll")                                             \
                for (int nt = 0; nt < 4; nt++) {                              \
                    mma16816(acc[mt][nt], ah, bh[nt]);                        \
                    mma16816(acc[mt][nt], ah, bl[nt]);                        \
                    mma16816(acc[mt][nt], al, bh[nt]);                        \
                }                                                             \
            }                                                                 \
        }                                                                     \
    } while (0)

    FETCH(0); STORE(0); __syncthreads();
    for (int ch = 0; ch < NCHK; ch++) {
        if (ch + 1 < NCHK) FETCH(ch + 1);
        COMPUTE(ch & 1);
        if (ch + 1 < NCHK) { STORE((ch + 1) & 1); __syncthreads(); }
    }

    // ---------------- epilogue ----------------
#pragma unroll
    for (int mt = 0; mt < 2; mt++)
#pragma unroll
    for (int nt = 0; nt < 4; nt++) {
        float* cc = acc[mt][nt];
        const int cpa = c0 + wn * 32 + nt * 8 + (l & 3) * 2;
        const int elo = e0 + wm * 32 + mt * 16 + (l >> 2);
        if (cpa >= ncols) continue;
        if (mode == M_BX) {
            Of[(size_t)cpa * D + elo] = cc[0];
            Of[(size_t)(cpa + 1) * D + elo] = cc[1];
            Of[(size_t)cpa * D + elo + 8] = cc[2];
            Of[(size_t)(cpa + 1) * D + elo + 8] = cc[3];
        } else if (mode == M_POW) {
            const int zds = i4sel(zd, z);
#pragma unroll
            for (int q = 0; q < 4; q++) {
                const int e = elo + ((q >> 1) << 3);
                const int c = cpa + (q & 1);
                const float v = cc[q];
                __nv_bfloat16 h = __float2bfloat16(v);
                __nv_bfloat16 lo = __float2bfloat16(v - __bfloat162float(h));
                const size_t rm = (size_t)zds * DDm + (size_t)e * D + c;
                const size_t tm = (size_t)zds * DDm + (size_t)c * D + e;
                g_PH[rm] = h; g_PL[rm] = lo;
                g_PTH[tm] = h; g_PTL[tm] = lo;
                if (zds == 21) g_Pf[(size_t)e * D + c] = v;
            }
        } else if (mode == M_SCAN) {
            const int b = cpa >> shN, j = cpa & mask;
            float* p0 = Of + ((size_t)b * Tl + (size_t)j * Cl + i) * D;
            float* p1 = p0 + (size_t)Cl * D;
            const float s0 = p0[elo] + cc[0];      p0[elo] = s0;
            const float s1 = p1[elo] + cc[1];      p1[elo] = s1;
            const float s2 = p0[elo + 8] + cc[2];  p0[elo + 8] = s2;
            const float s3 = p1[elo + 8] + cc[3];  p1[elo + 8] = s3;
            if (i == Cl - 1) {
                float* f = Pf + ((size_t)b * (mask + 1) + j + 1) * D;
                f[elo] = s0; f[elo + 8] = s2;      // j < mask always (j even)
                if (j + 1 < mask) {
                    float* f2 = Pf + ((size_t)b * (mask + 1) + j + 2) * D;
                    f2[elo] = s1; f2[elo + 8] = s3;
                }
            }
        } else {  // M_FIXZ
            const int b = cpa >> shN, j = cpa & mask;
            float* p0 = Of + ((size_t)b * Tl + (size_t)j * Cl + z) * D;
            float* p1 = p0 + (size_t)Cl * D;
            p0[elo] += cc[0]; p1[elo] += cc[1];
            p0[elo + 8] += cc[2]; p1[elo + 8] += cc[3];
        }
    }
#undef FETCH
#undef STORE
#undef COMPUTE
}

// ---------------- prep: split A (slot 0) and B (slot 22) ----------------
__global__ void prep_split(const float* __restrict__ A, const float* __restrict__ Bm) {
    const int idx = blockIdx.x * blockDim.x + threadIdx.x;  // 2*DDm
    const int off = idx & (DDm - 1);
    const int slot = (idx < DDm) ? 0 : 22;
    const float v = ((idx < DDm) ? A : Bm)[off];
    const int e = off >> 9, d = off & 511;
    __nv_bfloat16 h = __float2bfloat16(v);
    __nv_bfloat16 lo = __float2bfloat16(v - __bfloat162float(h));
    const size_t rm = (size_t)slot * DDm + off;
    const size_t tm = (size_t)slot * DDm + (size_t)d * D + e;
    g_PH[rm] = h; g_PL[rm] = lo;
    g_PTH[tm] = h; g_PTL[tm] = lo;
}

__global__ void seed_levels(const float* __restrict__ h0) {
    const int b = blockIdx.x, t = threadIdx.x;
    g_CB[(size_t)b * 512 * D + t] = h0[(size_t)b * D + t];
    g_DB[(size_t)b * 64 * D + t] = 0.f;
    g_EB[(size_t)b * 8 * D + t] = 0.f;
}

__global__ void __launch_bounds__(512) l4_scan() {
    __shared__ float s[D];
    const int b = blockIdx.x, t = threadIdx.x;
    s[t] = 0.f;
    __syncthreads();
    for (int p = 1; p < 8; p++) {
        const float* row = g_Pf + (size_t)t * D;
        float acc = 0.f;
#pragma unroll 8
        for (int k = 0; k < D; k += 4) {
            float4 a = *(const float4*)(row + k);
            acc += a.x * s[k] + a.y * s[k + 1] + a.z * s[k + 2] + a.w * s[k + 3];
        }
        acc += g_EB[((size_t)b * 8 + p) * D + t];
        __syncthreads();
        s[t] = acc;
        g_EB[((size_t)b * 8 + p) * D + t] = acc;
        __syncthreads();
    }
}

// ---------------- launcher ----------------
extern "C" void kernel_launch(void* const* d_in, const int* in_sizes, int n_in,
                              void* d_out, int out_size) {
    (void)in_sizes; (void)n_in; (void)out_size;
    const float* x  = (const float*)d_in[0];
    const float* h0 = (const float*)d_in[1];
    const float* A  = (const float*)d_in[2];
    const float* Bm = (const float*)d_in[3];
    float* out = (float*)d_out;

    static float *pCB = nullptr, *pDB, *pEB;
    if (!pCB) {
        cudaGetSymbolAddress((void**)&pCB, g_CB);
        cudaGetSymbolAddress((void**)&pDB, g_DB);
        cudaGetSymbolAddress((void**)&pEB, g_EB);
        cudaFuncSetAttribute(tstep, cudaFuncAttributeMaxDynamicSharedMemorySize, SMEMSZ);
    }
    const int4 zz = make_int4(0, 0, 0, 0);
#define TS(GX, GZ, ...) tstep<<<dim3(GX, 4, GZ), 256, SMEMSZ>>>(__VA_ARGS__)

    prep_split<<<2 * DDm / 256, 256>>>(A, Bm);

    // Bx: out[:,m] = B * x[m,:]   (32768 cols)
    TS(512, 1, x, out, nullptr, M_BX, 0, 0, 0, 0, 22, 32768, zz, zz, zz);

    // L1 local scan (A = slot 0), fold chunk ends -> CB[b, j+1]
    for (int i = 1; i < 8; i++)
        TS(64, 1, nullptr, out, pCB, M_SCAN, i, Tt, 8, 9, 0, 4096, zz, zz, zz);

    seed_levels<<<BSZ, D>>>(h0);

    // power tables (bf16 hi/lo in, fp32-accurate product re-split out)
#define PW(ZC, AZ, XZ, DZ) \
    TS(8, ZC, nullptr, nullptr, nullptr, M_POW, 0, 0, 0, 0, 0, 512, AZ, XZ, DZ)
    PW(1, make_int4(0,0,0,0),     make_int4(0,0,0,0),     make_int4(1,0,0,0));     // A^2
    PW(2, make_int4(1,1,0,0),     make_int4(0,1,0,0),     make_int4(2,3,0,0));     // A^3, A^4
    PW(4, make_int4(3,3,3,3),     make_int4(0,1,2,3),     make_int4(4,5,6,7));     // A^5..A^8
    PW(1, make_int4(7,0,0,0),     make_int4(7,0,0,0),     make_int4(8,0,0,0));     // A^16
    PW(2, make_int4(8,8,0,0),     make_int4(7,8,0,0),     make_int4(9,10,0,0));    // A^24, A^32
    PW(4, make_int4(10,10,10,10), make_int4(7,8,9,10),    make_int4(11,12,13,14)); // A^40..A^64
    PW(1, make_int4(14,0,0,0),    make_int4(14,0,0,0),    make_int4(15,0,0,0));    // A^128
    PW(2, make_int4(15,15,0,0),   make_int4(14,15,0,0),   make_int4(16,17,0,0));   // A^192, A^256
    PW(4, make_int4(17,17,17,17), make_int4(14,15,16,17), make_int4(18,19,20,21)); // A^320..A^512
#undef PW

    // L2 local scan on CB (A^8 = slot 7), fold -> DB
    for (int i = 1; i < 8; i++)
        TS(8, 1, nullptr, pCB, pDB, M_SCAN, i, 512, 8, 6, 7, 512, zz, zz, zz);

    // L3 local scan on DB (A^64 = slot 14), fold -> EB
    for (int i = 1; i < 8; i++)
        TS(1, 1, nullptr, pDB, pEB, M_SCAN, i, 64, 8, 3, 14, 64, zz, zz, zz);

    // L4 boundary scan (A^512 fp32)
    l4_scan<<<BSZ, D>>>();

    // L3 fixup: DB[:,8p+z] += A^{64(z+1)} * EB[:,p]
    TS(1, 8, pEB, pDB, nullptr, M_FIXZ, 0, 64, 8, 3, 14, 64, zz, zz, zz);
    // L2 fixup: CB[:,8m+z] += A^{8(z+1)} * DB[:,m]
    TS(8, 8, pDB, pCB, nullptr, M_FIXZ, 0, 512, 8, 6, 7, 512, zz, zz, zz);
    // L1 fixup: out[:,8j+z] += A^{z+1} * CB[:,j]
    TS(64, 8, pCB, out, nullptr, M_FIXZ, 0, Tt, 8, 9, 0, 4096, zz, zz, zz);
#undef TS
}